// round 2
// baseline (speedup 1.0000x reference)
#include <cuda_runtime.h>
#include <cuda_bf16.h>

// SSIM over (32,3,512,512) fp32 pairs, 7x7 box filters, interior-crop mean.
// Fused single pass: horizontal incremental 7-sums (4 cols/thread) +
// vertical running sums with an 8-row raw ring in shared memory.

namespace {
constexpr int W = 512;
constexpr int H = 512;
constexpr int NCH = 96;              // 32 * 3
constexpr int STRIPS = 4;
constexpr int SROWS = H / STRIPS;    // 128 output rows per block
constexpr int TPB = 128;
constexpr int CPT = 4;               // output columns per thread (128*4 = 512)
constexpr int RINGW = 520;           // 518 used (x = -3..514), padded for float4 tail
constexpr int NBLOCKS = NCH * STRIPS;
constexpr int CROP_LO = 3;
constexpr int CROP_HI = 508;         // inclusive; 506 rows/cols survive the crop
constexpr float C1 = 1e-4f;          // (0.01*1)^2
constexpr float C2 = 9e-4f;          // (0.03*1)^2
}

__device__ float g_partials[NBLOCKS];

// Load one image row (with x halo, zeros out of bounds) into registers.
__device__ __forceinline__ void prefetch_row(const float* __restrict__ p1,
                                             const float* __restrict__ p2,
                                             int r, int tid,
                                             float v1[5], float v2[5]) {
    const bool inr = ((unsigned)r < (unsigned)H);
    const float* row1 = p1 + (size_t)(inr ? r : 0) * W;
    const float* row2 = p2 + (size_t)(inr ? r : 0) * W;
#pragma unroll
    for (int k = 0; k < 5; k++) {
        int p = tid + k * TPB;       // ring position 0..517  (x = p - 3)
        int x = p - 3;
        float a = 0.f, b = 0.f;
        if (inr && p < W + 6 && (unsigned)x < (unsigned)W) {
            a = __ldg(row1 + x);
            b = __ldg(row2 + x);
        }
        v1[k] = a; v2[k] = b;
    }
}

__device__ __forceinline__ void store_row(float* __restrict__ d1,
                                          float* __restrict__ d2,
                                          int tid,
                                          const float v1[5], const float v2[5]) {
#pragma unroll
    for (int k = 0; k < 5; k++) {
        int p = tid + k * TPB;
        if (p < W + 6) { d1[p] = v1[k]; d2[p] = v2[k]; }
    }
}

// Accumulate (+/-) the 5 horizontal 7-sums for CPT consecutive outputs into vs.
// Reads 12 floats per image as 3 conflict-free LDS.128 (x0 is 16B aligned).
template <int SGN>
__device__ __forceinline__ void hsum_acc(const float* __restrict__ a,
                                         const float* __restrict__ b,
                                         int x0, float vs[5][CPT]) {
    float A[12], Bv[12];
    const float4* a4 = reinterpret_cast<const float4*>(a + x0);
    const float4* b4 = reinterpret_cast<const float4*>(b + x0);
#pragma unroll
    for (int q = 0; q < 3; q++) {
        float4 t = a4[q];
        A[4*q+0] = t.x; A[4*q+1] = t.y; A[4*q+2] = t.z; A[4*q+3] = t.w;
        float4 u = b4[q];
        Bv[4*q+0] = u.x; Bv[4*q+1] = u.y; Bv[4*q+2] = u.z; Bv[4*q+3] = u.w;
    }
    float s1 = 0.f, s2 = 0.f, s11 = 0.f, s22 = 0.f, s12 = 0.f;
#pragma unroll
    for (int i = 0; i < 7; i++) {
        s1 += A[i]; s2 += Bv[i];
        s11 = fmaf(A[i], A[i], s11);
        s22 = fmaf(Bv[i], Bv[i], s22);
        s12 = fmaf(A[i], Bv[i], s12);
    }
#pragma unroll
    for (int c = 0; c < CPT; c++) {
        if (c > 0) {                 // slide window one column to the right
            float an = A[c + 6], ao = A[c - 1];
            float bn = Bv[c + 6], bo = Bv[c - 1];
            s1 += an - ao;
            s2 += bn - bo;
            s11 += fmaf(an, an, -(ao * ao));
            s22 += fmaf(bn, bn, -(bo * bo));
            s12 += fmaf(an, bn, -(ao * bo));
        }
        if (SGN > 0) {
            vs[0][c] += s1; vs[1][c] += s2; vs[2][c] += s11;
            vs[3][c] += s22; vs[4][c] += s12;
        } else {
            vs[0][c] -= s1; vs[1][c] -= s2; vs[2][c] -= s11;
            vs[3][c] -= s22; vs[4][c] -= s12;
        }
    }
}

__global__ void __launch_bounds__(TPB) ssim_map_kernel(const float* __restrict__ img1,
                                                       const float* __restrict__ img2) {
    __shared__ __align__(16) float r1[8][RINGW];
    __shared__ __align__(16) float r2[8][RINGW];
    __shared__ float wsum[TPB / 32];

    const int blk = blockIdx.x;
    const int ch = blk / STRIPS;
    const int strip = blk - ch * STRIPS;
    const int y0 = strip * SROWS;
    const float* p1 = img1 + (size_t)ch * (W * H);
    const float* p2 = img2 + (size_t)ch * (W * H);
    const int tid = threadIdx.x;
    const int x0 = tid * CPT;

    // Fill the ring with rows y0-3 .. y0+3 (zeros outside the image).
#pragma unroll 1
    for (int r = y0 - 3; r <= y0 + 3; r++) {
        float v1[5], v2[5];
        prefetch_row(p1, p2, r, tid, v1, v2);
        store_row(r1[r & 7], r2[r & 7], tid, v1, v2);
    }
    __syncthreads();

    float vs[5][CPT];
#pragma unroll
    for (int q = 0; q < 5; q++)
#pragma unroll
        for (int c = 0; c < CPT; c++) vs[q][c] = 0.f;

#pragma unroll 1
    for (int r = y0 - 3; r <= y0 + 3; r++)
        hsum_acc<1>(r1[r & 7], r2[r & 7], x0, vs);

    // Prefetch the first mainloop row one iteration ahead (hides DRAM latency).
    float pf1[5], pf2[5];
    prefetch_row(p1, p2, y0 + 4, tid, pf1, pf2);

    constexpr float P = 1.0f / 49.0f;
    constexpr float CN = 49.0f / 48.0f;
    float lsum = 0.f;

#pragma unroll 1
    for (int y = y0; y < y0 + SROWS; y++) {
        if (y > y0) {
            __syncthreads();                       // prior reads of slot (y-5) done
            const int sn = (y + 3) & 7;            // entering row slot
            store_row(r1[sn], r2[sn], tid, pf1, pf2);
            prefetch_row(p1, p2, y + 4, tid, pf1, pf2);  // next row in flight
            __syncthreads();
            hsum_acc<1>(r1[sn], r2[sn], x0, vs);         // + entering row y+3
            const int so = (y - 4) & 7;
            hsum_acc<-1>(r1[so], r2[so], x0, vs);        // - leaving row y-4
        }
        if (y >= CROP_LO && y <= CROP_HI) {
#pragma unroll
            for (int c = 0; c < CPT; c++) {
                int x = x0 + c;
                if (x >= CROP_LO && x <= CROP_HI) {
                    float ux  = vs[0][c] * P, uy  = vs[1][c] * P;
                    float uxx = vs[2][c] * P, uyy = vs[3][c] * P, uxy = vs[4][c] * P;
                    float vx  = CN * (uxx - ux * ux);
                    float vy  = CN * (uyy - uy * uy);
                    float vxy = CN * (uxy - ux * uy);
                    float A1 = 2.f * ux * uy + C1;
                    float A2 = 2.f * vxy + C2;
                    float B1 = ux * ux + uy * uy + C1;
                    float B2 = vx + vy + C2;
                    lsum += __fdividef(A1 * A2, B1 * B2);
                }
            }
        }
    }

    // Deterministic block reduction: shfl within warp, fixed-order combine.
#pragma unroll
    for (int o = 16; o > 0; o >>= 1)
        lsum += __shfl_down_sync(0xffffffffu, lsum, o);
    if ((tid & 31) == 0) wsum[tid >> 5] = lsum;
    __syncthreads();
    if (tid == 0)
        g_partials[blk] = (wsum[0] + wsum[1]) + (wsum[2] + wsum[3]);
}

__global__ void __launch_bounds__(TPB) ssim_reduce_kernel(float* __restrict__ out) {
    __shared__ double sh[TPB];
    const int tid = threadIdx.x;
    double acc = 0.0;
#pragma unroll 1
    for (int i = tid; i < NBLOCKS; i += TPB) acc += (double)g_partials[i];
    sh[tid] = acc;
    __syncthreads();
#pragma unroll 1
    for (int o = TPB / 2; o > 0; o >>= 1) {
        if (tid < o) sh[tid] += sh[tid + o];
        __syncthreads();
    }
    if (tid == 0) {
        const double crop = (double)(CROP_HI - CROP_LO + 1);
        out[0] = (float)(sh[0] / ((double)NCH * crop * crop));
    }
}

extern "C" void kernel_launch(void* const* d_in, const int* in_sizes, int n_in,
                              void* d_out, int out_size) {
    (void)in_sizes; (void)n_in; (void)out_size;
    const float* img1 = (const float*)d_in[0];
    const float* img2 = (const float*)d_in[1];
    float* out = (float*)d_out;
    ssim_map_kernel<<<NBLOCKS, TPB>>>(img1, img2);
    ssim_reduce_kernel<<<1, TPB>>>(out);
}